// round 1
// baseline (speedup 1.0000x reference)
#include <cuda_runtime.h>
#include <cuda_bf16.h>

// CrossNetwork (DCN-v1): x_{i+1} = input * (x_i . w_i) + x_i + b_i, L=6 layers.
// Closed form: x_i = c_i * input + d_i with
//   d_{i+1} = d_i + b_i                      (row-independent vector)
//   e_i     = d_i . w_i                      (row-independent scalar)
//   S_i     = input . w_i                    (per-row scalar)
//   c_{i+1} = c_i * (S_i + 1) + e_i,  c_0 = 1
//   out     = c_L * input + d_L
//
// => one pass over input per row: 6 simultaneous dots, scalar chain, FMA epilogue.

#define D 1024
#define L 6
#define TPB 256   // 4 floats (one float4) per thread

__device__ float g_e[L];      // e_l = d_l . w_l
__device__ float g_dL[D];     // d_L = sum of all biases

// --- Prologue: one block of D threads computes d_L and e_l deterministically ---
__global__ void __launch_bounds__(D) cross_prologue(const float* __restrict__ W,
                                                    const float* __restrict__ b) {
    int j = threadIdx.x;          // 0..1023
    float d = 0.0f;
    float pe[L];
    #pragma unroll
    for (int l = 0; l < L; ++l) {
        pe[l] = d * W[l * D + j];
        d += b[l * D + j];
    }
    g_dL[j] = d;

    __shared__ float red[L][32];  // 32 warps
    int lane = j & 31, warp = j >> 5;
    #pragma unroll
    for (int l = 0; l < L; ++l) {
        float v = pe[l];
        #pragma unroll
        for (int o = 16; o > 0; o >>= 1) v += __shfl_xor_sync(0xFFFFFFFFu, v, o);
        if (lane == 0) red[l][warp] = v;
    }
    __syncthreads();
    if (j < L) {
        float t = 0.0f;
        #pragma unroll
        for (int k = 0; k < 32; ++k) t += red[j][k];   // deterministic serial sum
        g_e[j] = t;
    }
}

// --- Main kernel: one row per CTA ---
__global__ void __launch_bounds__(TPB) cross_main(const float* __restrict__ input,
                                                  const float* __restrict__ W,
                                                  float* __restrict__ out) {
    const int row = blockIdx.x;
    const int t = threadIdx.x;
    const int lane = t & 31, warp = t >> 5;

    const float4* inp4 = reinterpret_cast<const float4*>(input + (size_t)row * D);
    float4 xi = inp4[t];

    // 6 simultaneous dot-product partials; W float4 loads hit L1 after warmup.
    float acc[L];
    #pragma unroll
    for (int l = 0; l < L; ++l) {
        float4 w = __ldg(reinterpret_cast<const float4*>(W + l * D) + t);
        acc[l] = xi.x * w.x + xi.y * w.y + xi.z * w.z + xi.w * w.w;
    }

    __shared__ float red[L][TPB / 32];
    __shared__ float s_sum[L];
    #pragma unroll
    for (int l = 0; l < L; ++l) {
        float v = acc[l];
        #pragma unroll
        for (int o = 16; o > 0; o >>= 1) v += __shfl_xor_sync(0xFFFFFFFFu, v, o);
        if (lane == 0) red[l][warp] = v;
    }
    __syncthreads();
    if (t < L) {
        float v = 0.0f;
        #pragma unroll
        for (int k = 0; k < TPB / 32; ++k) v += red[t][k];
        s_sum[t] = v;
    }
    __syncthreads();

    // Scalar chain: c_{l+1} = c_l * (1 + S_l) + e_l
    float c = 1.0f;
    #pragma unroll
    for (int l = 0; l < L; ++l) c = c * (1.0f + s_sum[l]) + g_e[l];

    float4 d4 = __ldg(reinterpret_cast<const float4*>(g_dL) + t);
    float4 o;
    o.x = c * xi.x + d4.x;
    o.y = c * xi.y + d4.y;
    o.z = c * xi.z + d4.z;
    o.w = c * xi.w + d4.w;
    reinterpret_cast<float4*>(out + (size_t)row * D)[t] = o;
}

extern "C" void kernel_launch(void* const* d_in, const int* in_sizes, int n_in,
                              void* d_out, int out_size) {
    const float* input = (const float*)d_in[0];   // [B, D]
    const float* W     = (const float*)d_in[1];   // [L, D]
    const float* b     = (const float*)d_in[2];   // [L, D]
    float* out = (float*)d_out;

    int B = in_sizes[0] / D;

    cross_prologue<<<1, D>>>(W, b);
    cross_main<<<B, TPB>>>(input, W, out);
}